// round 17
// baseline (speedup 1.0000x reference)
#include <cuda_runtime.h>
#include <math.h>

#define HH 80
#define WW 80
#define CI 256
#define NF 128
#define NPIX (HH*WW)   // 6400
#define BATCH 2

// Scratch (device globals; no allocations allowed)
__device__ float g_qkv[3][BATCH][NPIX*NF];   // theta, phi(flat), g
__device__ float g_att[BATCH][NPIX*NF];      // attention output (n, c)

// ---------------- packed f32x2 helpers (FFMA2 via PTX) ----------------------
typedef unsigned long long ull;

__device__ __forceinline__ ull pack2(float lo, float hi) {
    ull r; asm("mov.b64 %0, {%1, %2};" : "=l"(r) : "f"(lo), "f"(hi)); return r;
}
__device__ __forceinline__ ull dup2(float v) { return pack2(v, v); }
__device__ __forceinline__ void fma2(ull& d, ull a, ull b) {
    asm("fma.rn.f32x2 %0, %1, %2, %3;" : "=l"(d) : "l"(a), "l"(b), "l"(d));
}
__device__ __forceinline__ ull mul2(ull a, ull b) {
    ull r; asm("mul.rn.f32x2 %0, %1, %2;" : "=l"(r) : "l"(a), "l"(b)); return r;
}
__device__ __forceinline__ float2 unpk(ull v) {
    float2 f; asm("mov.b64 {%0, %1}, %2;" : "=f"(f.x), "=f"(f.y) : "l"(v)); return f;
}

// ---------------------------------------------------------------------------
// Conv 3x3 SAME, CIN=256 -> CO=128 (theta/phi/g).  R15-exact (measured 443us)
// ---------------------------------------------------------------------------
#define PADQ 20
#define QR 2
#define CIH 128
__global__ __launch_bounds__(128) void conv_qkv_kernel(
    const float* __restrict__ x,
    const float* __restrict__ w0,
    const float* __restrict__ w1,
    const float* __restrict__ w2)
{
    extern __shared__ float s_in[];            // [4][CIH][PADQ] (18 used)
    const int x0 = blockIdx.x * 16;
    const int y0 = blockIdx.y * QR;
    const int b  = blockIdx.z / 3;
    const int cv = blockIdx.z % 3;
    const float* __restrict__ wgt = (cv == 0) ? w0 : ((cv == 1) ? w1 : w2);
    float* __restrict__ outp = g_qkv[cv][b];
    const int t = threadIdx.x;

    const int c2 = (t & 63) * 2;
    const int r  = t >> 6;    // 0..1

    ull acc[16];
#pragma unroll
    for (int p = 0; p < 16; p++) acc[p] = dup2(0.f);

    const int kstride = CI * NF;   // weight offset per kx

#pragma unroll 1
    for (int phase = 0; phase < 2; phase++) {
        const int cibase = phase * CIH;
        if (phase) __syncthreads();   // protect smem reuse between phases
        for (int i = t; i < (QR + 2) * 18 * CIH; i += 128) {
            int ci = i & (CIH - 1);
            int xi = (i >> 7) % 18;
            int rr = i / (18 * CIH);
            int gy = y0 - 1 + rr, gx = x0 - 1 + xi;
            float v = 0.f;
            if (gy >= 0 && gy < HH && gx >= 0 && gx < WW)
                v = x[((b * HH + gy) * WW + gx) * CI + cibase + ci];
            s_in[(rr * CIH + ci) * PADQ + xi] = v;
        }
        __syncthreads();

        for (int ky = 0; ky < 3; ky++) {
            const float* srow0 = &s_in[((r + ky) * CIH) * PADQ];
            const float* wbase = &wgt[(ky * 3 * CI + cibase) * NF + c2];
            ull a0 = *(const ull*)&wbase[0];
            ull a1 = *(const ull*)&wbase[kstride];
            ull a2 = *(const ull*)&wbase[2 * kstride];
            ull e0 = *(const ull*)&wbase[NF];
            ull e1 = *(const ull*)&wbase[kstride + NF];
            ull e2 = *(const ull*)&wbase[2 * kstride + NF];
#pragma unroll 1
            for (int ci = 0; ci < CIH; ci += 2) {
                ull u0 = a0, u1 = a1, u2 = a2;
                ull v0 = e0, v1 = e1, v2 = e2;
                if (ci + 2 < CIH) {
                    const float* wn = wbase + (ci + 2) * NF;
                    a0 = *(const ull*)&wn[0];
                    a1 = *(const ull*)&wn[kstride];
                    a2 = *(const ull*)&wn[2 * kstride];
                    e0 = *(const ull*)&wn[NF];
                    e1 = *(const ull*)&wn[kstride + NF];
                    e2 = *(const ull*)&wn[2 * kstride + NF];
                }
#pragma unroll
                for (int half = 0; half < 2; half++) {
                    const float* row = srow0 + (ci + half) * PADQ;
                    float4 wA = *(const float4*)&row[0];
                    float4 wB = *(const float4*)&row[4];
                    float4 wC = *(const float4*)&row[8];
                    float4 wD = *(const float4*)&row[12];
                    float2 wE = *(const float2*)&row[16];
                    ull wd[18];
                    wd[0]=dup2(wA.x);  wd[1]=dup2(wA.y);  wd[2]=dup2(wA.z);  wd[3]=dup2(wA.w);
                    wd[4]=dup2(wB.x);  wd[5]=dup2(wB.y);  wd[6]=dup2(wB.z);  wd[7]=dup2(wB.w);
                    wd[8]=dup2(wC.x);  wd[9]=dup2(wC.y);  wd[10]=dup2(wC.z); wd[11]=dup2(wC.w);
                    wd[12]=dup2(wD.x); wd[13]=dup2(wD.y); wd[14]=dup2(wD.z); wd[15]=dup2(wD.w);
                    wd[16]=dup2(wE.x); wd[17]=dup2(wE.y);
                    ull wv0 = half ? v0 : u0;
                    ull wv1 = half ? v1 : u1;
                    ull wv2 = half ? v2 : u2;
#pragma unroll
                    for (int p = 0; p < 16; p++) {
                        fma2(acc[p], wd[p],     wv0);
                        fma2(acc[p], wd[p + 1], wv1);
                        fma2(acc[p], wd[p + 2], wv2);
                    }
                }
            }
        }
    }
    const int nbase = (y0 + r) * WW + x0;
#pragma unroll
    for (int p = 0; p < 16; p++) {
        float2 v = unpk(acc[p]);
        *(float2*)&outp[(nbase + p) * NF + c2] = v;
    }
}

// ---------------------------------------------------------------------------
// Flash attention: 256 threads, warp shape 8tx x 4ty, frag 3x16, QROWS=96.
// B/G/P rows stored k-interleaved: off(j) = ((j&12)<<3) + ((j>>4)<<2), so each
// warp smem access = 8 distinct 16B chunks + 4-way broadcast = 1 wavefront.
// ---------------------------------------------------------------------------
#define LD  132
#define LDQ 100
#define QROWS 96
#define SM_Q 0
#define SM_B (128*LDQ)
#define SM_G (128*LDQ + 128*LD)

__device__ __forceinline__ int offj(int j) {
    return ((j & 12) << 3) + ((j >> 4) << 2);
}

__global__ __launch_bounds__(256, 1) void flash_kernel()
{
    extern __shared__ float sm[];
    float* Qst = sm + SM_Q;   // [c][i] transposed, i < 96
    float* Bs  = sm + SM_B;   // K-chunk (k-interleaved rows), then reused as P
    float* Gs  = sm + SM_G;   // G-chunk (k-interleaved rows)

    const int b  = blockIdx.y;
    const int q0 = blockIdx.x * QROWS;
    const float* __restrict__ theta = g_qkv[0][b];
    const float* __restrict__ phi   = g_qkv[1][b];
    const float* __restrict__ gmat  = g_qkv[2][b];

    const int t   = threadIdx.x;
    const int tx  = t & 7, ty = t >> 3;    // 8 x 32
    const int i0  = ty * 3;                // 3 rows per thread (96 total)
    const int j0  = tx * 16;               // 16 logical j per thread
    const int tx4 = tx * 4;

    // Load Q tile transposed: Qst[c*LDQ + i]  (rows clamped at edge tile)
    for (int idx = t; idx < QROWS * 128; idx += 256) {
        int i = idx >> 7, c = idx & 127;
        int qi = q0 + i; if (qi >= NPIX) qi = NPIX - 1;
        Qst[c * LDQ + i] = theta[qi * NF + c];
    }

    ull o2[3][8];
    float mrun[3], lrun[3];
#pragma unroll
    for (int ii = 0; ii < 3; ii++) {
        mrun[ii] = -1e30f; lrun[ii] = 0.f;
#pragma unroll
        for (int cp = 0; cp < 8; cp++) o2[ii][cp] = dup2(0.f);
    }
    __syncthreads();

    for (int km = 0; km < 50; km++) {
        const int m0 = km * 128;
        // stage B (phi rows) and G with k-interleaved row layout
        for (int idx = t; idx < 4096; idx += 256) {
            int rr = idx >> 5;
            int cc = (idx & 31) << 2;
            int po = offj(cc);
            *(float4*)&Bs[rr * LD + po] = *(const float4*)&phi[rr * NPIX + m0 + cc];
            *(float4*)&Gs[rr * LD + po] = *(const float4*)&gmat[(m0 + rr) * NF + cc];
        }
        __syncthreads();                 // (1) staging visible

        // GEMM1: S = Q @ B  (96x128x128), frag 3x16
        ull s2[3][8];
#pragma unroll
        for (int ii = 0; ii < 3; ii++)
#pragma unroll
            for (int jp = 0; jp < 8; jp++) s2[ii][jp] = dup2(0.f);

#pragma unroll 1
        for (int c = 0; c < 128; c += 2) {
#pragma unroll
            for (int cc2 = 0; cc2 < 2; cc2++) {
                const float* qrow = &Qst[(c + cc2) * LDQ + i0];
                ull av[3] = {dup2(qrow[0]), dup2(qrow[1]), dup2(qrow[2])};
                const float* brow = &Bs[(c + cc2) * LD + tx4];
                ull bv[8];
#pragma unroll
                for (int k = 0; k < 4; k++) {
                    ulonglong2 bb = *(const ulonglong2*)&brow[k * 32];
                    bv[2 * k] = bb.x; bv[2 * k + 1] = bb.y;
                }
#pragma unroll
                for (int ii = 0; ii < 3; ii++)
#pragma unroll
                    for (int jp = 0; jp < 8; jp++)
                        fma2(s2[ii][jp], av[ii], bv[jp]);
            }
        }
        __syncthreads();   // done reading Bs; safe to overwrite with P

        // Online softmax (reduction over the 8 tx lanes)
#pragma unroll
        for (int ii = 0; ii < 3; ii++) {
            float sv[16];
#pragma unroll
            for (int cp = 0; cp < 8; cp++) {
                float2 u = unpk(s2[ii][cp]);
                sv[2 * cp] = u.x; sv[2 * cp + 1] = u.y;
            }
            float mx = sv[0];
#pragma unroll
            for (int jj = 1; jj < 16; jj++) mx = fmaxf(mx, sv[jj]);
            mx = fmaxf(mx, __shfl_xor_sync(0xffffffffu, mx, 1));
            mx = fmaxf(mx, __shfl_xor_sync(0xffffffffu, mx, 2));
            mx = fmaxf(mx, __shfl_xor_sync(0xffffffffu, mx, 4));
            float mnew = fmaxf(mrun[ii], mx);
            float f = __expf(mrun[ii] - mnew);
            mrun[ii] = mnew;
            float sum = 0.f;
#pragma unroll
            for (int jj = 0; jj < 16; jj++) {
                float p = __expf(sv[jj] - mnew);
                sv[jj] = p;
                sum += p;
            }
            sum += __shfl_xor_sync(0xffffffffu, sum, 1);
            sum += __shfl_xor_sync(0xffffffffu, sum, 2);
            sum += __shfl_xor_sync(0xffffffffu, sum, 4);
            lrun[ii] = lrun[ii] * f + sum;
            ull f2v = dup2(f);
#pragma unroll
            for (int cp = 0; cp < 8; cp++)
                o2[ii][cp] = mul2(o2[ii][cp], f2v);
            // store P row (k-interleaved positions u*32 + tx4)
            float* prow = &Bs[(i0 + ii) * LD + tx4];
#pragma unroll
            for (int u = 0; u < 4; u++)
                *(float4*)&prow[u * 32] =
                    make_float4(sv[4*u], sv[4*u+1], sv[4*u+2], sv[4*u+3]);
        }
        __syncthreads();                 // (2) all P visible

        // GEMM2: O += P @ G  (16 channels per thread at j0)
#pragma unroll 1
        for (int j4 = 0; j4 < 128; j4 += 4) {
            const int pj4 = offj(j4);
            float4 pv4[3];
#pragma unroll
            for (int ii = 0; ii < 3; ii++)
                pv4[ii] = *(const float4*)&Bs[(i0 + ii) * LD + pj4];
#pragma unroll
            for (int jj = 0; jj < 4; jj++) {
                const float* grow = &Gs[(j4 + jj) * LD + tx4];
                ull gv[8];
#pragma unroll
                for (int k = 0; k < 4; k++) {
                    ulonglong2 gg = *(const ulonglong2*)&grow[k * 32];
                    gv[2 * k] = gg.x; gv[2 * k + 1] = gg.y;
                }
#pragma unroll
                for (int ii = 0; ii < 3; ii++) {
                    float pj = (jj == 0) ? pv4[ii].x : (jj == 1) ? pv4[ii].y
                             : (jj == 2) ? pv4[ii].z : pv4[ii].w;
                    ull pv = dup2(pj);
#pragma unroll
                    for (int cp = 0; cp < 8; cp++)
                        fma2(o2[ii][cp], pv, gv[cp]);
                }
            }
        }
        __syncthreads();                 // (3) GEMM2 reads done before next loads
    }

    // Epilogue: normalize and store (n, c) layout (channels j0..j0+15)
#pragma unroll
    for (int ii = 0; ii < 3; ii++) {
        int row = q0 + i0 + ii;
        if (row >= NPIX) continue;
        float inv = 1.f / lrun[ii];
        float ov[16];
#pragma unroll
        for (int cp = 0; cp < 8; cp++) {
            float2 u = unpk(o2[ii][cp]);
            ov[2 * cp] = u.x * inv; ov[2 * cp + 1] = u.y * inv;
        }
        float* dst = &g_att[b][row * NF + j0];
#pragma unroll
        for (int u = 0; u < 4; u++)
            *(float4*)&dst[u * 4] =
                make_float4(ov[4*u], ov[4*u+1], ov[4*u+2], ov[4*u+3]);
    }
}

// ---------------------------------------------------------------------------
// Final conv 3x3, 128 -> 256, + residual add, writes d_out. (R16-exact)
// Tile: 2 rows x 16 px x 256 co, 256 threads, smem 40KB.
// ---------------------------------------------------------------------------
#define PADF 20
__global__ __launch_bounds__(256) void conv_final_kernel(
    const float* __restrict__ x,
    const float* __restrict__ wc,
    float* __restrict__ out)
{
    extern __shared__ float s_in[];            // [4][NF][PADF] (18 used)
    const int x0 = blockIdx.x * 16;
    const int y0 = blockIdx.y * 2;
    const int b  = blockIdx.z;
    const int t  = threadIdx.x;
    const float* __restrict__ ain = g_att[b];

    for (int i = t; i < 4 * 18 * NF; i += 256) {
        int ci = i & (NF - 1);
        int xi = (i >> 7) % 18;
        int r  = i / (18 * NF);
        int gy = y0 - 1 + r, gx = x0 - 1 + xi;
        float v = 0.f;
        if (gy >= 0 && gy < HH && gx >= 0 && gx < WW)
            v = ain[(gy * WW + gx) * NF + ci];
        s_in[(r * NF + ci) * PADF + xi] = v;
    }
    __syncthreads();

    const int c2 = (t & 127) * 2;
    const int r  = t >> 7;    // 0..1

    ull acc[16];
#pragma unroll
    for (int p = 0; p < 16; p++) acc[p] = dup2(0.f);

    const int kstride = NF * CI;   // weight offset per kx

    for (int ky = 0; ky < 3; ky++) {
        const float* srow0 = &s_in[((r + ky) * NF) * PADF];
        const float* wbase = &wc[(ky * 3 * NF) * CI + c2];
        ull a0 = *(const ull*)&wbase[0];
        ull a1 = *(const ull*)&wbase[kstride];
        ull a2 = *(const ull*)&wbase[2 * kstride];
        ull e0 = *(const ull*)&wbase[CI];
        ull e1 = *(const ull*)&wbase[kstride + CI];
        ull e2 = *(const ull*)&wbase[2 * kstride + CI];
#pragma unroll 1
        for (int ci = 0; ci < NF; ci += 2) {
            ull u0 = a0, u1 = a1, u2 = a2;
            ull v0 = e0, v1 = e1, v2 = e2;
            if (ci + 2 < NF) {
                const float* wn = wbase + (ci + 2) * CI;
                a0 = *(const ull*)&wn[0];
                a1 = *(const ull*)&wn[kstride];
                a2 = *(const ull*)&wn[2 * kstride];
                e0 = *(const ull*)&wn[CI];
                e1 = *(const ull*)&wn[kstride + CI];
                e2 = *(const ull*)&wn[2 * kstride + CI];
            }
#pragma unroll
            for (int half = 0; half < 2; half++) {
                const float* row = srow0 + (ci + half) * PADF;
                float4 wA = *(const float4*)&row[0];
                float4 wB = *(const float4*)&row[4];
                float4 wC = *(const float4*)&row[8];
                float4 wD = *(const float4*)&row[12];
                float2 wE = *(const float2*)&row[16];
                ull wd[18];
                wd[0]=dup2(wA.x);  wd[1]=dup2(wA.y);  wd[2]=dup2(wA.z);  wd[3]=dup2(wA.w);
                wd[4]=dup2(wB.x);  wd[5]=dup2(wB.y);  wd[6]=dup2(wB.z);  wd[7]=dup2(wB.w);
                wd[8]=dup2(wC.x);  wd[9]=dup2(wC.y);  wd[10]=dup2(wC.z); wd[11]=dup2(wC.w);
                wd[12]=dup2(wD.x); wd[13]=dup2(wD.y); wd[14]=dup2(wD.z); wd[15]=dup2(wD.w);
                wd[16]=dup2(wE.x); wd[17]=dup2(wE.y);
                ull wv0 = half ? v0 : u0;
                ull wv1 = half ? v1 : u1;
                ull wv2 = half ? v2 : u2;
#pragma unroll
                for (int p = 0; p < 16; p++) {
                    fma2(acc[p], wd[p],     wv0);
                    fma2(acc[p], wd[p + 1], wv1);
                    fma2(acc[p], wd[p + 2], wv2);
                }
            }
        }
    }
#pragma unroll
    for (int p = 0; p < 16; p++) {
        float2 v = unpk(acc[p]);
        int gi = ((b * HH + y0 + r) * WW + x0 + p) * CI + c2;
        float2 xv = *(const float2*)&x[gi];
        *(float2*)&out[gi] = make_float2(xv.x + v.x, xv.y + v.y);
    }
}

// ---------------------------------------------------------------------------
extern "C" void kernel_launch(void* const* d_in, const int* in_sizes, int n_in,
                              void* d_out, int out_size)
{
    const float* x  = (const float*)d_in[0];
    const float* wt = (const float*)d_in[1];
    const float* wp = (const float*)d_in[2];
    const float* wg = (const float*)d_in[3];
    const float* wc = (const float*)d_in[4];
    float* out = (float*)d_out;

    const int smem_qkv   = (QR + 2) * CIH * PADQ * 4;         // 40960
    const int smem_flash = (128 * LDQ + 2 * 128 * LD) * 4;    // 186368
    const int smem_final = 4 * NF * PADF * 4;                 // 40960

    cudaFuncSetAttribute(conv_qkv_kernel,   cudaFuncAttributeMaxDynamicSharedMemorySize, smem_qkv);
    cudaFuncSetAttribute(flash_kernel,      cudaFuncAttributeMaxDynamicSharedMemorySize, smem_flash);
    cudaFuncSetAttribute(conv_final_kernel, cudaFuncAttributeMaxDynamicSharedMemorySize, smem_final);

    const int qtiles = (NPIX + QROWS - 1) / QROWS;            // 67

    conv_qkv_kernel<<<dim3(5, HH / QR, 6), 128, smem_qkv>>>(x, wt, wp, wg);
    flash_kernel<<<dim3(qtiles, 2), 256, smem_flash>>>();
    conv_final_kernel<<<dim3(5, HH / 2, 2), 256, smem_final>>>(x, wc, out);
}